// round 2
// baseline (speedup 1.0000x reference)
#include <cuda_runtime.h>
#include <math.h>

#define NN 50000
#define EE 800000
#define FF 256
static constexpr size_t NF = (size_t)NN * FF;
static constexpr size_t EF = (size_t)EE * FF;

// ---------------- scratch (static device memory; no allocs allowed) ----------------
__device__ float g_hA[NF];
__device__ float g_hB[NF];
__device__ float g_eA[EF];
__device__ float g_eB[EF];
__device__ float g_etmp[EF];
__device__ float g_hW[5][NF];          // 0=Ws,1=Wd,2=Wself,3=Wf,4=Wb
__device__ float g_aggf[NF];
__device__ float g_aggb[NF];
__device__ float g_htmp[NF];
__device__ float g_logf[EE];
__device__ float g_logb[EE];
__device__ unsigned g_maxf[NN];
__device__ unsigned g_maxb[NN];
__device__ float g_denf[NN];
__device__ float g_denb[NN];
__device__ double g_bnsum[2 * FF];     // e-BN: sum, sumsq (fp64 accum for accuracy)
__device__ double g_bnsumh[2 * FF];    // h-BN
__device__ float g_scaleE[FF], g_shiftE[FF];
__device__ float g_scaleH[FF], g_shiftH[FF];

// monotone float<->uint encoding for atomicMax over floats
__device__ __forceinline__ unsigned f2u(float f) {
    unsigned u = __float_as_uint(f);
    return (u & 0x80000000u) ? ~u : (u | 0x80000000u);
}
__device__ __forceinline__ float u2f(unsigned u) {
    return (u & 0x80000000u) ? __uint_as_float(u & 0x7FFFFFFFu) : __uint_as_float(~u);
}

// ---------------- zero per-layer accumulators ----------------
__global__ void zero_layer() {
    size_t i = (size_t)blockIdx.x * blockDim.x + threadIdx.x;
    if (i < NF) { g_aggf[i] = 0.f; g_aggb[i] = 0.f; }
    if (i < EE) { g_logf[i] = 0.f; g_logb[i] = 0.f; }
    if (i < NN) { g_maxf[i] = 0u; g_maxb[i] = 0u; g_denf[i] = 0.f; g_denb[i] = 0.f; }
    if (i < 2 * FF) { g_bnsum[i] = 0.0; g_bnsumh[i] = 0.0; }
}

// ---------------- 128x128x16 SGEMM, 8x8 microtile, 256 threads ----------------
// EDGE=true: C = A@W + gather(hWs,src) + gather(hWd,dst), fused BN col-sums and
//            attention row-dots. EDGE=false: C = A@W into g_hW[widx].
template <bool EDGE, bool GUARD>
__global__ void __launch_bounds__(256)
gemm128(const float* __restrict__ A, const float* __restrict__ W, int M, int widx,
        const int* __restrict__ src, const int* __restrict__ dst,
        const float* __restrict__ attf, const float* __restrict__ attb) {
    __shared__ float As[16][128];
    __shared__ float Bs[16][128];
    const int tid = threadIdx.x;
    const int tx = tid & 15, ty = tid >> 4;
    const int rowBase = blockIdx.x * 128;
    const int colBase = blockIdx.y * 128;

    float acc[8][8];
#pragma unroll
    for (int i = 0; i < 8; i++)
#pragma unroll
        for (int j = 0; j < 8; j++) acc[i][j] = 0.f;

    const int aRow = tid >> 2, aCol = (tid & 3) << 2;
    const int bRow = tid >> 5, bCol = (tid & 31) << 2;

    for (int k0 = 0; k0 < FF; k0 += 16) {
#pragma unroll
        for (int h2 = 0; h2 < 2; h2++) {
            int r = aRow + h2 * 64;
            int gr = rowBase + r;
            float4 v = make_float4(0.f, 0.f, 0.f, 0.f);
            if (!GUARD || gr < M) v = *(const float4*)(A + (size_t)gr * FF + k0 + aCol);
            As[aCol][r] = v.x; As[aCol + 1][r] = v.y; As[aCol + 2][r] = v.z; As[aCol + 3][r] = v.w;
        }
#pragma unroll
        for (int h2 = 0; h2 < 2; h2++) {
            int r = bRow + h2 * 8;
            *(float4*)&Bs[r][bCol] = *(const float4*)(W + (size_t)(k0 + r) * FF + colBase + bCol);
        }
        __syncthreads();
#pragma unroll
        for (int k = 0; k < 16; k++) {
            float ra[8], rb[8];
#pragma unroll
            for (int i = 0; i < 8; i++) ra[i] = As[k][ty * 8 + i];
#pragma unroll
            for (int j = 0; j < 8; j++) rb[j] = Bs[k][tx * 8 + j];
#pragma unroll
            for (int i = 0; i < 8; i++)
#pragma unroll
                for (int j = 0; j < 8; j++) acc[i][j] += ra[i] * rb[j];
        }
        __syncthreads();
    }

    const int row0 = rowBase + ty * 8;
    const int col0 = colBase + tx * 8;
    float* C = EDGE ? g_etmp : g_hW[widx];

    if (EDGE) {
#pragma unroll
        for (int i = 0; i < 8; i++) {
            int r = row0 + i;
            int s = src[r], d = dst[r];
            const float4* ps = (const float4*)(&g_hW[0][(size_t)s * FF + col0]);
            const float4* pd = (const float4*)(&g_hW[1][(size_t)d * FF + col0]);
            float4 a0 = ps[0], a1 = ps[1], b0 = pd[0], b1 = pd[1];
            acc[i][0] += a0.x + b0.x; acc[i][1] += a0.y + b0.y;
            acc[i][2] += a0.z + b0.z; acc[i][3] += a0.w + b0.w;
            acc[i][4] += a1.x + b1.x; acc[i][5] += a1.y + b1.y;
            acc[i][6] += a1.z + b1.z; acc[i][7] += a1.w + b1.w;
        }
    }

#pragma unroll
    for (int i = 0; i < 8; i++) {
        int r = row0 + i;
        if (GUARD && r >= M) continue;
        float4 v0 = make_float4(acc[i][0], acc[i][1], acc[i][2], acc[i][3]);
        float4 v1 = make_float4(acc[i][4], acc[i][5], acc[i][6], acc[i][7]);
        *(float4*)(C + (size_t)r * FF + col0) = v0;
        *(float4*)(C + (size_t)r * FF + col0 + 4) = v1;
    }

    if (EDGE) {
        float* red = &As[0][0];  // 2048 floats of scratch
        // ---- BN column sums/sumsq ----
        if (tid < 128) { red[tid] = 0.f; red[128 + tid] = 0.f; }
        __syncthreads();
#pragma unroll
        for (int j = 0; j < 8; j++) {
            float s = 0.f, s2 = 0.f;
#pragma unroll
            for (int i = 0; i < 8; i++) { float v = acc[i][j]; s += v; s2 += v * v; }
            atomicAdd(&red[tx * 8 + j], s);
            atomicAdd(&red[128 + tx * 8 + j], s2);
        }
        __syncthreads();
        if (tid < 128) {
            atomicAdd(&g_bnsum[colBase + tid], (double)red[tid]);
            atomicAdd(&g_bnsum[FF + colBase + tid], (double)red[128 + tid]);
        }
        __syncthreads();
        // ---- attention logit row dots ----
        if (tid < 128) { red[tid] = 0.f; red[128 + tid] = 0.f; }
        __syncthreads();
        float af[8], ab[8];
#pragma unroll
        for (int j = 0; j < 8; j++) { af[j] = attf[col0 + j]; ab[j] = attb[col0 + j]; }
#pragma unroll
        for (int i = 0; i < 8; i++) {
            float df = 0.f, db = 0.f;
#pragma unroll
            for (int j = 0; j < 8; j++) { df += acc[i][j] * af[j]; db += acc[i][j] * ab[j]; }
            atomicAdd(&red[ty * 8 + i], df);
            atomicAdd(&red[128 + ty * 8 + i], db);
        }
        __syncthreads();
        if (tid < 128) {
            atomicAdd(&g_logf[rowBase + tid], red[tid]);
            atomicAdd(&g_logb[rowBase + tid], red[128 + tid]);
        }
    }
}

// ---------------- BN finalize: scale/shift per feature ----------------
__global__ void bn_final(const float* __restrict__ g, const float* __restrict__ b,
                         int isH, float invM) {
    int f = threadIdx.x;
    const double* sums = isH ? g_bnsumh : g_bnsum;
    float mu = (float)(sums[f] * (double)invM);
    float var = (float)(sums[FF + f] * (double)invM) - mu * mu;
    float sc = rsqrtf(var + 1e-5f) * g[f];
    float sh = b[f] - mu * sc;
    if (isH) { g_scaleH[f] = sc; g_shiftH[f] = sh; }
    else     { g_scaleE[f] = sc; g_shiftE[f] = sh; }
}

// ---------------- out = xin + relu(tmp*scale + shift) ----------------
__global__ void residual_bn_relu(const float* __restrict__ xin, float* __restrict__ out,
                                 int isH, size_t total) {
    size_t i = ((size_t)blockIdx.x * blockDim.x + threadIdx.x) * 4;
    if (i >= total) return;
    const float* tmp = isH ? g_htmp : g_etmp;
    const float* scale = isH ? g_scaleH : g_scaleE;
    const float* shift = isH ? g_shiftH : g_shiftE;
    int c = (int)(i & (FF - 1));
    float4 x = *(const float4*)(xin + i);
    float4 t = *(const float4*)(tmp + i);
    float4 o;
    o.x = x.x + fmaxf(fmaf(t.x, scale[c],     shift[c]),     0.f);
    o.y = x.y + fmaxf(fmaf(t.y, scale[c + 1], shift[c + 1]), 0.f);
    o.z = x.z + fmaxf(fmaf(t.z, scale[c + 2], shift[c + 2]), 0.f);
    o.w = x.w + fmaxf(fmaf(t.w, scale[c + 3], shift[c + 3]), 0.f);
    *(float4*)(out + i) = o;
}

// ---------------- attention: leaky-relu + segment max ----------------
__global__ void att_max(const int* __restrict__ src, const int* __restrict__ dst) {
    int e = blockIdx.x * blockDim.x + threadIdx.x;
    if (e >= EE) return;
    float lf = g_logf[e]; lf = lf > 0.f ? lf : 0.2f * lf; g_logf[e] = lf;
    float lb = g_logb[e]; lb = lb > 0.f ? lb : 0.2f * lb; g_logb[e] = lb;
    atomicMax(&g_maxf[dst[e]], f2u(lf));
    atomicMax(&g_maxb[src[e]], f2u(lb));
}

// ---------------- attention: exp + segment sum ----------------
__global__ void att_exp(const int* __restrict__ src, const int* __restrict__ dst) {
    int e = blockIdx.x * blockDim.x + threadIdx.x;
    if (e >= EE) return;
    int d = dst[e], s = src[e];
    float exf = expf(g_logf[e] - u2f(g_maxf[d]));
    g_logf[e] = exf;
    atomicAdd(&g_denf[d], exf);
    float exb = expf(g_logb[e] - u2f(g_maxb[s]));
    g_logb[e] = exb;
    atomicAdd(&g_denb[s], exb);
}

// ---------------- aggregation: agg_f[dst] += alpha_f * hWf[src] (and symmetric) ----------------
__global__ void __launch_bounds__(256)
aggregate(const int* __restrict__ src, const int* __restrict__ dst) {
    int lane = threadIdx.x & 63;
    int e = blockIdx.x * 4 + (threadIdx.x >> 6);
    if (e >= EE) return;
    int s = src[e], d = dst[e];
    float af = g_logf[e] / (g_denf[d] + 1e-9f);
    float ab = g_logb[e] / (g_denb[s] + 1e-9f);
    float4 vf = *(const float4*)(&g_hW[3][(size_t)s * FF + lane * 4]);
    float4 vb = *(const float4*)(&g_hW[4][(size_t)d * FF + lane * 4]);
    float* pf = &g_aggf[(size_t)d * FF + lane * 4];
    float* pb = &g_aggb[(size_t)s * FF + lane * 4];
    atomicAdd(pf + 0, af * vf.x); atomicAdd(pf + 1, af * vf.y);
    atomicAdd(pf + 2, af * vf.z); atomicAdd(pf + 3, af * vf.w);
    atomicAdd(pb + 0, ab * vb.x); atomicAdd(pb + 1, ab * vb.y);
    atomicAdd(pb + 2, ab * vb.z); atomicAdd(pb + 3, ab * vb.w);
}

// ---------------- h_tmp = hWself + agg_f + agg_b, fused BN stats ----------------
__global__ void htmp_stats() {
    int col = threadIdx.x;
    int row0 = blockIdx.x * 64;
    float s = 0.f, s2 = 0.f;
    for (int r = 0; r < 64; r++) {
        int row = row0 + r;
        if (row >= NN) break;
        size_t idx = (size_t)row * FF + col;
        float v = g_hW[2][idx] + g_aggf[idx] + g_aggb[idx];
        g_htmp[idx] = v;
        s += v; s2 += v * v;
    }
    atomicAdd(&g_bnsumh[col], (double)s);
    atomicAdd(&g_bnsumh[FF + col], (double)s2);
}

// ---------------- host ----------------
extern "C" void kernel_launch(void* const* d_in, const int* in_sizes, int n_in,
                              void* d_out, int out_size) {
    const float* h0    = (const float*)d_in[0];
    const float* e0    = (const float*)d_in[1];
    const int*   src   = (const int*)d_in[2];
    const int*   dst   = (const int*)d_in[3];
    const float* We    = (const float*)d_in[4];
    const float* Ws    = (const float*)d_in[5];
    const float* Wd    = (const float*)d_in[6];
    const float* Wself = (const float*)d_in[7];
    const float* Wf    = (const float*)d_in[8];
    const float* Wb    = (const float*)d_in[9];
    const float* att_f = (const float*)d_in[10];
    const float* att_b = (const float*)d_in[11];
    const float* ge    = (const float*)d_in[12];
    const float* be    = (const float*)d_in[13];
    const float* gh    = (const float*)d_in[14];
    const float* bh    = (const float*)d_in[15];

    float* out_h = (float*)d_out;
    float* out_e = out_h + NF;

    float *hA, *hB, *eA, *eB;
    cudaGetSymbolAddress((void**)&hA, g_hA);
    cudaGetSymbolAddress((void**)&hB, g_hB);
    cudaGetSymbolAddress((void**)&eA, g_eA);
    cudaGetSymbolAddress((void**)&eB, g_eB);

    const float* Wptr[5] = {Ws, Wd, Wself, Wf, Wb};

    const float* hin = h0;
    const float* ein = e0;
    for (int l = 0; l < 4; l++) {
        float* hout = (l == 3) ? out_h : ((l & 1) ? hB : hA);
        float* eout = (l == 3) ? out_e : ((l & 1) ? eB : eA);

        zero_layer<<<50000, 256>>>();

        for (int w = 0; w < 5; w++)
            gemm128<false, true><<<dim3(391, 2), 256>>>(
                hin, Wptr[w] + (size_t)l * FF * FF, NN, w,
                nullptr, nullptr, nullptr, nullptr);

        gemm128<true, false><<<dim3(6250, 2), 256>>>(
            ein, We + (size_t)l * FF * FF, EE, -1,
            src, dst, att_f + l * FF, att_b + l * FF);

        bn_final<<<1, 256>>>(ge + l * FF, be + l * FF, 0, 1.0f / EE);
        residual_bn_relu<<<200000, 256>>>(ein, eout, 0, EF);

        att_max<<<3125, 256>>>(src, dst);
        att_exp<<<3125, 256>>>(src, dst);
        aggregate<<<200000, 256>>>(src, dst);

        htmp_stats<<<782, 256>>>();
        bn_final<<<1, 256>>>(gh + l * FF, bh + l * FF, 1, 1.0f / NN);
        residual_bn_relu<<<12500, 256>>>(hin, hout, 1, NF);

        hin = hout;
        ein = eout;
    }
}

// round 3
// speedup vs baseline: 1.0004x; 1.0004x over previous
#include <cuda_runtime.h>
#include <math.h>

#define NN 50000
#define EE 800000
#define FF 256
static constexpr size_t NF = (size_t)NN * FF;
static constexpr size_t EF = (size_t)EE * FF;

// ---------------- scratch (static device memory; no allocs allowed) ----------------
__device__ float g_hA[NF];
__device__ float g_hB[NF];
__device__ float g_eA[EF];
__device__ float g_eB[EF];
__device__ float g_etmp[EF];
__device__ float g_hW[5][NF];          // 0=Ws,1=Wd,2=Wself,3=Wf,4=Wb
__device__ float g_aggf[NF];
__device__ float g_aggb[NF];
__device__ float g_htmp[NF];
__device__ float g_logf[EE];
__device__ float g_logb[EE];
__device__ unsigned g_maxf[NN];
__device__ unsigned g_maxb[NN];
__device__ float g_denf[NN];
__device__ float g_denb[NN];
__device__ double g_bnsum[2 * FF];     // e-BN: sum, sumsq (fp64 accum for accuracy)
__device__ double g_bnsumh[2 * FF];    // h-BN
__device__ float g_scaleE[FF], g_shiftE[FF];
__device__ float g_scaleH[FF], g_shiftH[FF];

// monotone float<->uint encoding for atomicMax over floats
__device__ __forceinline__ unsigned f2u(float f) {
    unsigned u = __float_as_uint(f);
    return (u & 0x80000000u) ? ~u : (u | 0x80000000u);
}
__device__ __forceinline__ float u2f(unsigned u) {
    return (u & 0x80000000u) ? __uint_as_float(u & 0x7FFFFFFFu) : __uint_as_float(~u);
}

// ---------------- zero per-layer accumulators ----------------
__global__ void zero_layer() {
    size_t i = (size_t)blockIdx.x * blockDim.x + threadIdx.x;
    if (i < NF) { g_aggf[i] = 0.f; g_aggb[i] = 0.f; }
    if (i < EE) { g_logf[i] = 0.f; g_logb[i] = 0.f; }
    if (i < NN) { g_maxf[i] = 0u; g_maxb[i] = 0u; g_denf[i] = 0.f; g_denb[i] = 0.f; }
    if (i < 2 * FF) { g_bnsum[i] = 0.0; g_bnsumh[i] = 0.0; }
}

// ---------------- 128x128x16 SGEMM, 8x8 microtile, 256 threads ----------------
// EDGE=true: C = A@W + gather(hWs,src) + gather(hWd,dst), fused BN col-sums and
//            attention row-dots. EDGE=false: C = A@W into g_hW[widx].
template <bool EDGE, bool GUARD>
__global__ void __launch_bounds__(256)
gemm128(const float* __restrict__ A, const float* __restrict__ W, int M, int widx,
        const int* __restrict__ src, const int* __restrict__ dst,
        const float* __restrict__ attf, const float* __restrict__ attb) {
    __shared__ float As[16][128];
    __shared__ float Bs[16][128];
    const int tid = threadIdx.x;
    const int tx = tid & 15, ty = tid >> 4;
    const int rowBase = blockIdx.x * 128;
    const int colBase = blockIdx.y * 128;

    float acc[8][8];
#pragma unroll
    for (int i = 0; i < 8; i++)
#pragma unroll
        for (int j = 0; j < 8; j++) acc[i][j] = 0.f;

    const int aRow = tid >> 2, aCol = (tid & 3) << 2;
    const int bRow = tid >> 5, bCol = (tid & 31) << 2;

    for (int k0 = 0; k0 < FF; k0 += 16) {
#pragma unroll
        for (int h2 = 0; h2 < 2; h2++) {
            int r = aRow + h2 * 64;
            int gr = rowBase + r;
            float4 v = make_float4(0.f, 0.f, 0.f, 0.f);
            if (!GUARD || gr < M) v = *(const float4*)(A + (size_t)gr * FF + k0 + aCol);
            As[aCol][r] = v.x; As[aCol + 1][r] = v.y; As[aCol + 2][r] = v.z; As[aCol + 3][r] = v.w;
        }
#pragma unroll
        for (int h2 = 0; h2 < 2; h2++) {
            int r = bRow + h2 * 8;
            *(float4*)&Bs[r][bCol] = *(const float4*)(W + (size_t)(k0 + r) * FF + colBase + bCol);
        }
        __syncthreads();
#pragma unroll
        for (int k = 0; k < 16; k++) {
            float ra[8], rb[8];
#pragma unroll
            for (int i = 0; i < 8; i++) ra[i] = As[k][ty * 8 + i];
#pragma unroll
            for (int j = 0; j < 8; j++) rb[j] = Bs[k][tx * 8 + j];
#pragma unroll
            for (int i = 0; i < 8; i++)
#pragma unroll
                for (int j = 0; j < 8; j++) acc[i][j] += ra[i] * rb[j];
        }
        __syncthreads();
    }

    const int row0 = rowBase + ty * 8;
    const int col0 = colBase + tx * 8;
    float* C = EDGE ? g_etmp : g_hW[widx];

    if (EDGE) {
#pragma unroll
        for (int i = 0; i < 8; i++) {
            int r = row0 + i;
            int s = src[r], d = dst[r];
            const float4* ps = (const float4*)(&g_hW[0][(size_t)s * FF + col0]);
            const float4* pd = (const float4*)(&g_hW[1][(size_t)d * FF + col0]);
            float4 a0 = ps[0], a1 = ps[1], b0 = pd[0], b1 = pd[1];
            acc[i][0] += a0.x + b0.x; acc[i][1] += a0.y + b0.y;
            acc[i][2] += a0.z + b0.z; acc[i][3] += a0.w + b0.w;
            acc[i][4] += a1.x + b1.x; acc[i][5] += a1.y + b1.y;
            acc[i][6] += a1.z + b1.z; acc[i][7] += a1.w + b1.w;
        }
    }

#pragma unroll
    for (int i = 0; i < 8; i++) {
        int r = row0 + i;
        if (GUARD && r >= M) continue;
        float4 v0 = make_float4(acc[i][0], acc[i][1], acc[i][2], acc[i][3]);
        float4 v1 = make_float4(acc[i][4], acc[i][5], acc[i][6], acc[i][7]);
        *(float4*)(C + (size_t)r * FF + col0) = v0;
        *(float4*)(C + (size_t)r * FF + col0 + 4) = v1;
    }

    if (EDGE) {
        float* red = &As[0][0];  // 2048 floats of scratch
        // ---- BN column sums/sumsq ----
        if (tid < 128) { red[tid] = 0.f; red[128 + tid] = 0.f; }
        __syncthreads();
#pragma unroll
        for (int j = 0; j < 8; j++) {
            float s = 0.f, s2 = 0.f;
#pragma unroll
            for (int i = 0; i < 8; i++) { float v = acc[i][j]; s += v; s2 += v * v; }
            atomicAdd(&red[tx * 8 + j], s);
            atomicAdd(&red[128 + tx * 8 + j], s2);
        }
        __syncthreads();
        if (tid < 128) {
            atomicAdd(&g_bnsum[colBase + tid], (double)red[tid]);
            atomicAdd(&g_bnsum[FF + colBase + tid], (double)red[128 + tid]);
        }
        __syncthreads();
        // ---- attention logit row dots ----
        if (tid < 128) { red[tid] = 0.f; red[128 + tid] = 0.f; }
        __syncthreads();
        float af[8], ab[8];
#pragma unroll
        for (int j = 0; j < 8; j++) { af[j] = attf[col0 + j]; ab[j] = attb[col0 + j]; }
#pragma unroll
        for (int i = 0; i < 8; i++) {
            float df = 0.f, db = 0.f;
#pragma unroll
            for (int j = 0; j < 8; j++) { df += acc[i][j] * af[j]; db += acc[i][j] * ab[j]; }
            atomicAdd(&red[ty * 8 + i], df);
            atomicAdd(&red[128 + ty * 8 + i], db);
        }
        __syncthreads();
        if (tid < 128) {
            atomicAdd(&g_logf[rowBase + tid], red[tid]);
            atomicAdd(&g_logb[rowBase + tid], red[128 + tid]);
        }
    }
}

// ---------------- BN finalize: scale/shift per feature ----------------
__global__ void bn_final(const float* __restrict__ g, const float* __restrict__ b,
                         int isH, float invM) {
    int f = threadIdx.x;
    const double* sums = isH ? g_bnsumh : g_bnsum;
    float mu = (float)(sums[f] * (double)invM);
    float var = (float)(sums[FF + f] * (double)invM) - mu * mu;
    float sc = rsqrtf(var + 1e-5f) * g[f];
    float sh = b[f] - mu * sc;
    if (isH) { g_scaleH[f] = sc; g_shiftH[f] = sh; }
    else     { g_scaleE[f] = sc; g_shiftE[f] = sh; }
}

// ---------------- out = xin + relu(tmp*scale + shift) ----------------
__global__ void residual_bn_relu(const float* __restrict__ xin, float* __restrict__ out,
                                 int isH, size_t total) {
    size_t i = ((size_t)blockIdx.x * blockDim.x + threadIdx.x) * 4;
    if (i >= total) return;
    const float* tmp = isH ? g_htmp : g_etmp;
    const float* scale = isH ? g_scaleH : g_scaleE;
    const float* shift = isH ? g_shiftH : g_shiftE;
    int c = (int)(i & (FF - 1));
    float4 x = *(const float4*)(xin + i);
    float4 t = *(const float4*)(tmp + i);
    float4 o;
    o.x = x.x + fmaxf(fmaf(t.x, scale[c],     shift[c]),     0.f);
    o.y = x.y + fmaxf(fmaf(t.y, scale[c + 1], shift[c + 1]), 0.f);
    o.z = x.z + fmaxf(fmaf(t.z, scale[c + 2], shift[c + 2]), 0.f);
    o.w = x.w + fmaxf(fmaf(t.w, scale[c + 3], shift[c + 3]), 0.f);
    *(float4*)(out + i) = o;
}

// ---------------- attention: leaky-relu + segment max ----------------
__global__ void att_max(const int* __restrict__ src, const int* __restrict__ dst) {
    int e = blockIdx.x * blockDim.x + threadIdx.x;
    if (e >= EE) return;
    float lf = g_logf[e]; lf = lf > 0.f ? lf : 0.2f * lf; g_logf[e] = lf;
    float lb = g_logb[e]; lb = lb > 0.f ? lb : 0.2f * lb; g_logb[e] = lb;
    atomicMax(&g_maxf[dst[e]], f2u(lf));
    atomicMax(&g_maxb[src[e]], f2u(lb));
}

// ---------------- attention: exp + segment sum ----------------
__global__ void att_exp(const int* __restrict__ src, const int* __restrict__ dst) {
    int e = blockIdx.x * blockDim.x + threadIdx.x;
    if (e >= EE) return;
    int d = dst[e], s = src[e];
    float exf = expf(g_logf[e] - u2f(g_maxf[d]));
    g_logf[e] = exf;
    atomicAdd(&g_denf[d], exf);
    float exb = expf(g_logb[e] - u2f(g_maxb[s]));
    g_logb[e] = exb;
    atomicAdd(&g_denb[s], exb);
}

// ---------------- aggregation: agg_f[dst] += alpha_f * hWf[src] (and symmetric) ----------------
__global__ void __launch_bounds__(256)
aggregate(const int* __restrict__ src, const int* __restrict__ dst) {
    int lane = threadIdx.x & 63;
    int e = blockIdx.x * 4 + (threadIdx.x >> 6);
    if (e >= EE) return;
    int s = src[e], d = dst[e];
    float af = g_logf[e] / (g_denf[d] + 1e-9f);
    float ab = g_logb[e] / (g_denb[s] + 1e-9f);
    float4 vf = *(const float4*)(&g_hW[3][(size_t)s * FF + lane * 4]);
    float4 vb = *(const float4*)(&g_hW[4][(size_t)d * FF + lane * 4]);
    float* pf = &g_aggf[(size_t)d * FF + lane * 4];
    float* pb = &g_aggb[(size_t)s * FF + lane * 4];
    atomicAdd(pf + 0, af * vf.x); atomicAdd(pf + 1, af * vf.y);
    atomicAdd(pf + 2, af * vf.z); atomicAdd(pf + 3, af * vf.w);
    atomicAdd(pb + 0, ab * vb.x); atomicAdd(pb + 1, ab * vb.y);
    atomicAdd(pb + 2, ab * vb.z); atomicAdd(pb + 3, ab * vb.w);
}

// ---------------- h_tmp = hWself + agg_f + agg_b, fused BN stats ----------------
__global__ void htmp_stats() {
    int col = threadIdx.x;
    int row0 = blockIdx.x * 64;
    float s = 0.f, s2 = 0.f;
    for (int r = 0; r < 64; r++) {
        int row = row0 + r;
        if (row >= NN) break;
        size_t idx = (size_t)row * FF + col;
        float v = g_hW[2][idx] + g_aggf[idx] + g_aggb[idx];
        g_htmp[idx] = v;
        s += v; s2 += v * v;
    }
    atomicAdd(&g_bnsumh[col], (double)s);
    atomicAdd(&g_bnsumh[FF + col], (double)s2);
}

// ---------------- host ----------------
extern "C" void kernel_launch(void* const* d_in, const int* in_sizes, int n_in,
                              void* d_out, int out_size) {
    const float* h0    = (const float*)d_in[0];
    const float* e0    = (const float*)d_in[1];
    const int*   src   = (const int*)d_in[2];
    const int*   dst   = (const int*)d_in[3];
    const float* We    = (const float*)d_in[4];
    const float* Ws    = (const float*)d_in[5];
    const float* Wd    = (const float*)d_in[6];
    const float* Wself = (const float*)d_in[7];
    const float* Wf    = (const float*)d_in[8];
    const float* Wb    = (const float*)d_in[9];
    const float* att_f = (const float*)d_in[10];
    const float* att_b = (const float*)d_in[11];
    const float* ge    = (const float*)d_in[12];
    const float* be    = (const float*)d_in[13];
    const float* gh    = (const float*)d_in[14];
    const float* bh    = (const float*)d_in[15];

    float* out_h = (float*)d_out;
    float* out_e = out_h + NF;

    float *hA, *hB, *eA, *eB;
    cudaGetSymbolAddress((void**)&hA, g_hA);
    cudaGetSymbolAddress((void**)&hB, g_hB);
    cudaGetSymbolAddress((void**)&eA, g_eA);
    cudaGetSymbolAddress((void**)&eB, g_eB);

    const float* Wptr[5] = {Ws, Wd, Wself, Wf, Wb};

    const float* hin = h0;
    const float* ein = e0;
    for (int l = 0; l < 4; l++) {
        float* hout = (l == 3) ? out_h : ((l & 1) ? hB : hA);
        float* eout = (l == 3) ? out_e : ((l & 1) ? eB : eA);

        zero_layer<<<50000, 256>>>();

        for (int w = 0; w < 5; w++)
            gemm128<false, true><<<dim3(391, 2), 256>>>(
                hin, Wptr[w] + (size_t)l * FF * FF, NN, w,
                nullptr, nullptr, nullptr, nullptr);

        gemm128<true, false><<<dim3(6250, 2), 256>>>(
            ein, We + (size_t)l * FF * FF, EE, -1,
            src, dst, att_f + l * FF, att_b + l * FF);

        bn_final<<<1, 256>>>(ge + l * FF, be + l * FF, 0, 1.0f / EE);
        residual_bn_relu<<<200000, 256>>>(ein, eout, 0, EF);

        att_max<<<3125, 256>>>(src, dst);
        att_exp<<<3125, 256>>>(src, dst);
        aggregate<<<200000, 256>>>(src, dst);

        htmp_stats<<<782, 256>>>();
        bn_final<<<1, 256>>>(gh + l * FF, bh + l * FF, 1, 1.0f / NN);
        residual_bn_relu<<<12500, 256>>>(hin, hout, 1, NF);

        hin = hout;
        ein = eout;
    }
}

// round 14
// speedup vs baseline: 1.7037x; 1.7029x over previous
#include <cuda_runtime.h>
#include <cuda_bf16.h>
#include <math.h>
#include <stdint.h>

#define NN 50000
#define NPAD 50048
#define EE 800000
#define FF 256
static constexpr size_t NF  = (size_t)NN * FF;
static constexpr size_t NFP = (size_t)NPAD * FF;
static constexpr size_t EF  = (size_t)EE * FF;

// ---------------- static device scratch ----------------
__device__ float g_eA[EF];
__device__ float g_eB[EF];
__device__ float g_hA[NF];
__device__ float g_hB[NF];
__device__ float g_etmp[EF];
__device__ float g_hW[5][NF];          // 0=Ws,1=Wd,2=Wself,3=Wf,4=Wb
__device__ float g_htmp[NF];
__device__ float g_logf[EE];
__device__ float g_logb[EE];
__device__ unsigned g_maxf[NN];
__device__ unsigned g_maxb[NN];
__device__ float g_denf[NN];
__device__ float g_denb[NN];
__device__ double g_bnsum[2 * FF];
__device__ double g_bnsumh[2 * FF];
__device__ float g_scaleE[FF], g_shiftE[FF];
__device__ float g_scaleH[FF], g_shiftH[FF];
__device__ __nv_bfloat16 g_ehi[EF];
__device__ __nv_bfloat16 g_elo[EF];
__device__ __nv_bfloat16 g_hhi[NFP];
__device__ __nv_bfloat16 g_hlo[NFP];
__device__ __nv_bfloat16 g_Wthi[24 * FF * FF];  // [l*6+m][n][k]; m 0..4 node mats, 5=We
__device__ __nv_bfloat16 g_Wtlo[24 * FF * FF];
// CSR
__device__ int g_degf[NN], g_degb[NN];
__device__ int g_startf[NN], g_startb[NN];
__device__ int g_curf[NN], g_curb[NN];
__device__ int g_permf[EE], g_permb[EE];

// ---------------- helpers ----------------
__device__ __forceinline__ unsigned f2u(float f) {
    unsigned u = __float_as_uint(f);
    return (u & 0x80000000u) ? ~u : (u | 0x80000000u);
}
__device__ __forceinline__ float u2f(unsigned u) {
    return (u & 0x80000000u) ? __uint_as_float(u & 0x7FFFFFFFu) : __uint_as_float(~u);
}
__device__ __forceinline__ uint32_t smem_u32(const void* p) {
    uint32_t a;
    asm("{ .reg .u64 t; cvta.to.shared.u64 t, %1; cvt.u32.u64 %0, t; }" : "=r"(a) : "l"(p));
    return a;
}
__device__ __forceinline__ void split_bf16(float x, __nv_bfloat16& h, __nv_bfloat16& l) {
    h = __float2bfloat16_rn(x);
    l = __float2bfloat16_rn(x - __bfloat162float(h));
}
__device__ __forceinline__ void cp16(uint32_t s, const void* g) {
    asm volatile("cp.async.cg.shared.global [%0], [%1], 16;" :: "r"(s), "l"(g) : "memory");
}
__device__ __forceinline__ void ldsm_x4(uint32_t& r0, uint32_t& r1, uint32_t& r2, uint32_t& r3,
                                        uint32_t addr) {
    asm volatile("ldmatrix.sync.aligned.m8n8.x4.shared.b16 {%0,%1,%2,%3}, [%4];"
                 : "=r"(r0), "=r"(r1), "=r"(r2), "=r"(r3) : "r"(addr));
}
__device__ __forceinline__ void mma16816(float* c, uint32_t a0, uint32_t a1, uint32_t a2,
                                         uint32_t a3, uint32_t b0, uint32_t b1) {
    asm volatile(
        "mma.sync.aligned.m16n8k16.row.col.f32.bf16.bf16.f32 "
        "{%0,%1,%2,%3}, {%4,%5,%6,%7}, {%8,%9}, {%0,%1,%2,%3};"
        : "+f"(c[0]), "+f"(c[1]), "+f"(c[2]), "+f"(c[3])
        : "r"(a0), "r"(a1), "r"(a2), "r"(a3), "r"(b0), "r"(b1));
}

// ---------------- mma.sync GEMM: C[128,128] = A[128,256] @ Wt^T ----------------
// 3-pass bf16 split. Operand tiles: rows padded to 40 bf16 (80B) for ldmatrix.
// Stage: Ahi[128][40] Alo Bhi[128][40] Blo = 40960B; 3 stages = 122880B.
#define STAGE_B 40960
#define ARR_B 10240
#define SMEM_DYN (3 * STAGE_B)

__device__ __forceinline__ void load_chunk_mma(
    uint32_t sb, int stage, int c, int tid, int rowBase, int bRow0, size_t matOff,
    const __nv_bfloat16* __restrict__ Ahi, const __nv_bfloat16* __restrict__ Alo,
    const __nv_bfloat16* __restrict__ Bhi, const __nv_bfloat16* __restrict__ Blo) {
    uint32_t st = sb + (uint32_t)stage * STAGE_B;
#pragma unroll
    for (int i = 0; i < 8; i++) {
        int j = tid + i * 256;
        int arr = j >> 9, rem = j & 511, row = rem >> 2, part = rem & 3;
        uint32_t sm = st + (uint32_t)arr * ARR_B + (uint32_t)row * 80 + (uint32_t)part * 16;
        const __nv_bfloat16* g;
        if (arr == 0)      g = Ahi + (size_t)(rowBase + row) * FF + c * 32 + part * 8;
        else if (arr == 1) g = Alo + (size_t)(rowBase + row) * FF + c * 32 + part * 8;
        else if (arr == 2) g = Bhi + matOff + (size_t)(bRow0 + row) * FF + c * 32 + part * 8;
        else               g = Blo + matOff + (size_t)(bRow0 + row) * FF + c * 32 + part * 8;
        cp16(sm, g);
    }
    asm volatile("cp.async.commit_group;" ::: "memory");
}

template <int EDGE>
__global__ void __launch_bounds__(256, 1)
gemm_mma(const __nv_bfloat16* __restrict__ Ahi, const __nv_bfloat16* __restrict__ Alo,
         const __nv_bfloat16* __restrict__ Bhi, const __nv_bfloat16* __restrict__ Blo,
         const int* __restrict__ src, const int* __restrict__ dst,
         const float* __restrict__ attf, const float* __restrict__ attb) {
    extern __shared__ __align__(16) char smem[];
    const uint32_t sb = smem_u32(smem);
    const int tid = threadIdx.x;
    const int lane = tid & 31, wid = tid >> 5;
    const int rowBase = blockIdx.x * 128;
    const int bly = blockIdx.y;
    const int colBase = EDGE ? bly * 128 : (bly & 1) * 128;
    const size_t matOff = EDGE ? 0 : (size_t)(bly >> 1) * FF * FF;
    const int wrow = (wid & 3) * 32;
    const int wcol = (wid >> 2) * 64;

    float acc[2][8][4];
#pragma unroll
    for (int mt = 0; mt < 2; mt++)
#pragma unroll
        for (int nt = 0; nt < 8; nt++)
#pragma unroll
            for (int k = 0; k < 4; k++) acc[mt][nt][k] = 0.f;

    load_chunk_mma(sb, 0, 0, tid, rowBase, colBase, matOff, Ahi, Alo, Bhi, Blo);
    load_chunk_mma(sb, 1, 1, tid, rowBase, colBase, matOff, Ahi, Alo, Bhi, Blo);
    load_chunk_mma(sb, 2, 2, tid, rowBase, colBase, matOff, Ahi, Alo, Bhi, Blo);

    for (int c = 0; c < 8; c++) {
        if (c < 6)       asm volatile("cp.async.wait_group 2;" ::: "memory");
        else if (c == 6) asm volatile("cp.async.wait_group 1;" ::: "memory");
        else             asm volatile("cp.async.wait_group 0;" ::: "memory");
        __syncthreads();
        uint32_t stg = sb + (uint32_t)(c % 3) * STAGE_B;
#pragma unroll
        for (int p = 0; p < 3; p++) {
            uint32_t aOff = stg + ((p == 2) ? ARR_B : 0);
            uint32_t bOff = stg + 2 * ARR_B + ((p == 1) ? ARR_B : 0);
#pragma unroll
            for (int k16 = 0; k16 < 2; k16++) {
                uint32_t aAddr = aOff + (uint32_t)(wrow + (lane & 15)) * 80 +
                                 (uint32_t)(k16 * 16 + (lane >> 4) * 8) * 2;
                uint32_t a0, a1, a2, a3, a4, a5, a6, a7;
                ldsm_x4(a0, a1, a2, a3, aAddr);
                ldsm_x4(a4, a5, a6, a7, aAddr + 16 * 80);
                uint32_t b[16];
#pragma unroll
                for (int g = 0; g < 4; g++) {
                    // B fragment: Wt is [n][k] (K-major rows) == col-major B, so NON-trans
                    // ldmatrix of Wt rows yields {B[k][n],B[k+1][n]} pairs directly.
                    uint32_t bAddr = bOff +
                        (uint32_t)(wcol + g * 16 + ((lane >> 4) << 3) + (lane & 7)) * 80 +
                        (uint32_t)(k16 * 16 + ((lane >> 3) & 1) * 8) * 2;
                    ldsm_x4(b[g * 4], b[g * 4 + 1], b[g * 4 + 2], b[g * 4 + 3], bAddr);
                }
#pragma unroll
                for (int nt = 0; nt < 8; nt++) {
                    mma16816(acc[0][nt], a0, a1, a2, a3, b[nt * 2], b[nt * 2 + 1]);
                    mma16816(acc[1][nt], a4, a5, a6, a7, b[nt * 2], b[nt * 2 + 1]);
                }
            }
        }
        __syncthreads();
        if (c + 3 < 8)
            load_chunk_mma(sb, (c + 3) % 3, c + 3, tid, rowBase, colBase, matOff,
                           Ahi, Alo, Bhi, Blo);
    }

    // ---------------- epilogue ----------------
    const int quad = lane >> 2, q2 = (lane & 3) * 2;
    if (EDGE) {
        float* Csm = (float*)smem;   // 128 x 132
        __syncthreads();
#pragma unroll
        for (int mt = 0; mt < 2; mt++)
#pragma unroll
            for (int nt = 0; nt < 8; nt++) {
                int r = wrow + 16 * mt + quad;
                int cc = wcol + 8 * nt + q2;
                *(float2*)&Csm[r * 132 + cc] = make_float2(acc[mt][nt][0], acc[mt][nt][1]);
                *(float2*)&Csm[(r + 8) * 132 + cc] = make_float2(acc[mt][nt][2], acc[mt][nt][3]);
            }
        __syncthreads();
        {
            int r = tid >> 1, half = tid & 1;
            int gr = rowBase + r;
            int cl0 = half * 64;
            int s = src[gr], d = dst[gr];
            const float4* hs = (const float4*)(g_hW[0] + (size_t)s * FF + colBase + cl0);
            const float4* hd = (const float4*)(g_hW[1] + (size_t)d * FF + colBase + cl0);
            float4* op = (float4*)(g_etmp + (size_t)gr * FF + colBase + cl0);
            float4* cp_ = (float4*)(Csm + r * 132 + cl0);
            const float4* af4 = (const float4*)(attf + colBase + cl0);
            const float4* ab4 = (const float4*)(attb + colBase + cl0);
            float df = 0.f, db = 0.f;
#pragma unroll
            for (int q = 0; q < 16; q++) {
                float4 v = cp_[q], a = hs[q], bb = hd[q];
                v.x += a.x + bb.x; v.y += a.y + bb.y; v.z += a.z + bb.z; v.w += a.w + bb.w;
                float4 af = af4[q], ab = ab4[q];
                df += v.x * af.x + v.y * af.y + v.z * af.z + v.w * af.w;
                db += v.x * ab.x + v.y * ab.y + v.z * ab.z + v.w * ab.w;
                op[q] = v;
                cp_[q] = v;
            }
            atomicAdd(&g_logf[gr], df);
            atomicAdd(&g_logb[gr], db);
        }
        __syncthreads();
        if (tid < 128) {
            float s = 0.f, s2 = 0.f;
#pragma unroll 8
            for (int r = 0; r < 128; r++) {
                float v = Csm[r * 132 + tid];
                s += v; s2 += v * v;
            }
            atomicAdd(&g_bnsum[colBase + tid], (double)s);
            atomicAdd(&g_bnsum[FF + colBase + tid], (double)s2);
        }
    } else {
        const int widx = bly >> 1;
        float* W = g_hW[widx];
#pragma unroll
        for (int mt = 0; mt < 2; mt++) {
            int gr = rowBase + wrow + 16 * mt + quad;
#pragma unroll
            for (int nt = 0; nt < 8; nt++) {
                int gcol = colBase + wcol + 8 * nt + q2;
                if (gr < NN)
                    *(float2*)&W[(size_t)gr * FF + gcol] = make_float2(acc[mt][nt][0], acc[mt][nt][1]);
                if (gr + 8 < NN)
                    *(float2*)&W[(size_t)(gr + 8) * FF + gcol] = make_float2(acc[mt][nt][2], acc[mt][nt][3]);
            }
        }
    }
}

// ---------------- weight transpose + split (once) ----------------
__global__ void wconv(const float* __restrict__ We, const float* __restrict__ Ws,
                      const float* __restrict__ Wd, const float* __restrict__ Wself,
                      const float* __restrict__ Wf, const float* __restrict__ Wb) {
    int mi = blockIdx.y, l = mi / 6, m = mi % 6;
    const float* W = (m == 0) ? Ws : (m == 1) ? Wd : (m == 2) ? Wself :
                     (m == 3) ? Wf : (m == 4) ? Wb : We;
    W += (size_t)l * FF * FF;
    __nv_bfloat16* hi = g_Wthi + (size_t)mi * FF * FF;
    __nv_bfloat16* lo = g_Wtlo + (size_t)mi * FF * FF;
    int idx = (blockIdx.x * 256 + threadIdx.x) * 4;
#pragma unroll
    for (int t = 0; t < 4; t++) {
        int o = idx + t, n = o >> 8, k = o & 255;
        __nv_bfloat16 h, lw;
        split_bf16(W[(size_t)k * FF + n], h, lw);   // Wt[n][k] = W[k][n]
        hi[o] = h; lo[o] = lw;
    }
}

// ---------------- fp32 -> bf16 hi/lo split ----------------
__global__ void conv_split(const float* __restrict__ x, __nv_bfloat16* __restrict__ hi,
                           __nv_bfloat16* __restrict__ lo, size_t total) {
    size_t i = ((size_t)blockIdx.x * blockDim.x + threadIdx.x) * 4;
    if (i >= total) return;
    float4 v = *(const float4*)(x + i);
    __nv_bfloat16 h0, l0, h1, l1, h2, l2, h3, l3;
    split_bf16(v.x, h0, l0); split_bf16(v.y, h1, l1);
    split_bf16(v.z, h2, l2); split_bf16(v.w, h3, l3);
    __nv_bfloat162 a, b, c, d;
    a.x = h0; a.y = h1; b.x = h2; b.y = h3;
    c.x = l0; c.y = l1; d.x = l2; d.y = l3;
    *(__nv_bfloat162*)(hi + i) = a; *(__nv_bfloat162*)(hi + i + 2) = b;
    *(__nv_bfloat162*)(lo + i) = c; *(__nv_bfloat162*)(lo + i + 2) = d;
}

// ---------------- once-per-call init ----------------
__global__ void init_zero() {
    int i = blockIdx.x * 256 + threadIdx.x;
    if (i < NN) { g_degf[i] = 0; g_degb[i] = 0; }
    if (i < 48 * FF) {
        size_t base = (size_t)NN * FF + i;
        g_hhi[base] = __float2bfloat16(0.f);
        g_hlo[base] = __float2bfloat16(0.f);
    }
}
__global__ void count_deg(const int* __restrict__ src, const int* __restrict__ dst) {
    int e = blockIdx.x * 256 + threadIdx.x;
    if (e >= EE) return;
    atomicAdd(&g_degf[dst[e]], 1);
    atomicAdd(&g_degb[src[e]], 1);
}
__global__ void scan_starts() {   // single block, 1024 threads
    __shared__ int sh[1024];
    __shared__ int carry;
    int tid = threadIdx.x;
    for (int a = 0; a < 2; a++) {
        const int* deg = a ? g_degb : g_degf;
        int* start = a ? g_startb : g_startf;
        int* cur = a ? g_curb : g_curf;
        if (tid == 0) carry = 0;
        __syncthreads();
        for (int base = 0; base < NN; base += 1024) {
            int n = base + tid;
            int v = (n < NN) ? deg[n] : 0;
            sh[tid] = v;
            __syncthreads();
            for (int off = 1; off < 1024; off <<= 1) {
                int t = (tid >= off) ? sh[tid - off] : 0;
                __syncthreads();
                sh[tid] += t;
                __syncthreads();
            }
            int excl = sh[tid] - v + carry;
            if (n < NN) { start[n] = excl; cur[n] = excl; }
            __syncthreads();
            if (tid == 0) carry += sh[1023];
            __syncthreads();
        }
    }
}
__global__ void fill_perm(const int* __restrict__ src, const int* __restrict__ dst) {
    int e = blockIdx.x * 256 + threadIdx.x;
    if (e >= EE) return;
    g_permf[atomicAdd(&g_curf[dst[e]], 1)] = e;
    g_permb[atomicAdd(&g_curb[src[e]], 1)] = e;
}

// ---------------- per-layer zero ----------------
__global__ void zero_layer() {
    int i = blockIdx.x * 256 + threadIdx.x;
    if (i < EE) { g_logf[i] = 0.f; g_logb[i] = 0.f; }
    if (i < NN) { g_maxf[i] = 0u; g_maxb[i] = 0u; g_denf[i] = 0.f; g_denb[i] = 0.f; }
    if (i < 2 * FF) { g_bnsum[i] = 0.0; g_bnsumh[i] = 0.0; }
}

// ---------------- BN finalize ----------------
__global__ void bn_final(const float* __restrict__ g, const float* __restrict__ b,
                         int isH, float invM) {
    int f = threadIdx.x;
    const double* sums = isH ? g_bnsumh : g_bnsum;
    float mu = (float)(sums[f] * (double)invM);
    float var = (float)(sums[FF + f] * (double)invM) - mu * mu;
    float sc = rsqrtf(var + 1e-5f) * g[f];
    float sh = b[f] - mu * sc;
    if (isH) { g_scaleH[f] = sc; g_shiftH[f] = sh; }
    else     { g_scaleE[f] = sc; g_shiftE[f] = sh; }
}

// ---------------- out = xin + relu(tmp*scale+shift), fused bf16 split ----------------
template <int ISH>
__global__ void residual_split(const float* __restrict__ xin, float* __restrict__ out,
                               __nv_bfloat16* __restrict__ hi, __nv_bfloat16* __restrict__ lo,
                               size_t total) {
    size_t i = ((size_t)blockIdx.x * blockDim.x + threadIdx.x) * 4;
    if (i >= total) return;
    const float* tmp = ISH ? g_htmp : g_etmp;
    const float* scale = ISH ? g_scaleH : g_scaleE;
    const float* shift = ISH ? g_shiftH : g_shiftE;
    int c = (int)(i & (FF - 1));
    float4 x = *(const float4*)(xin + i);
    float4 t = *(const float4*)(tmp + i);
    float4 o;
    o.x = x.x + fmaxf(fmaf(t.x, scale[c],     shift[c]),     0.f);
    o.y = x.y + fmaxf(fmaf(t.y, scale[c + 1], shift[c + 1]), 0.f);
    o.z = x.z + fmaxf(fmaf(t.z, scale[c + 2], shift[c + 2]), 0.f);
    o.w = x.w + fmaxf(fmaf(t.w, scale[c + 3], shift[c + 3]), 0.f);
    *(float4*)(out + i) = o;
    __nv_bfloat16 h0, l0, h1, l1, h2, l2, h3, l3;
    split_bf16(o.x, h0, l0); split_bf16(o.y, h1, l1);
    split_bf16(o.z, h2, l2); split_bf16(o.w, h3, l3);
    __nv_bfloat162 a, b, cc, d;
    a.x = h0; a.y = h1; b.x = h2; b.y = h3;
    cc.x = l0; cc.y = l1; d.x = l2; d.y = l3;
    *(__nv_bfloat162*)(hi + i) = a; *(__nv_bfloat162*)(hi + i + 2) = b;
    *(__nv_bfloat162*)(lo + i) = cc; *(__nv_bfloat162*)(lo + i + 2) = d;
}

// ---------------- attention ----------------
__global__ void att_max(const int* __restrict__ src, const int* __restrict__ dst) {
    int e = blockIdx.x * 256 + threadIdx.x;
    if (e >= EE) return;
    float lf = g_logf[e]; lf = lf > 0.f ? lf : 0.2f * lf; g_logf[e] = lf;
    float lb = g_logb[e]; lb = lb > 0.f ? lb : 0.2f * lb; g_logb[e] = lb;
    atomicMax(&g_maxf[dst[e]], f2u(lf));
    atomicMax(&g_maxb[src[e]], f2u(lb));
}
__global__ void att_exp(const int* __restrict__ src, const int* __restrict__ dst) {
    int e = blockIdx.x * 256 + threadIdx.x;
    if (e >= EE) return;
    int d = dst[e], s = src[e];
    float exf = expf(g_logf[e] - u2f(g_maxf[d]));
    g_logf[e] = exf;
    atomicAdd(&g_denf[d], exf);
    float exb = expf(g_logb[e] - u2f(g_maxb[s]));
    g_logb[e] = exb;
    atomicAdd(&g_denb[s], exb);
}

// ---------------- CSR aggregation + htmp + h BN stats ----------------
__global__ void __launch_bounds__(256)
agg_htmp(const int* __restrict__ src, const int* __restrict__ dst) {
    __shared__ float red[512];
    int tid = threadIdx.x;
    red[tid] = 0.f; red[tid + 256] = 0.f;
    __syncthreads();
    int g = tid >> 6, lane = tid & 63;
    int n = blockIdx.x * 4 + g;
    if (n < NN) {
        int col = lane * 4;
        float4 acc = make_float4(0.f, 0.f, 0.f, 0.f);
        int s0 = g_startf[n], e0 = s0 + g_degf[n];
        float rdf = 1.f / (g_denf[n] + 1e-9f);
        for (int i = s0; i < e0; i++) {
            int e = g_permf[i];
            float a = g_logf[e] * rdf;
            float4 v = *(const float4*)(&g_hW[3][(size_t)src[e] * FF + col]);
            acc.x += a * v.x; acc.y += a * v.y; acc.z += a * v.z; acc.w += a * v.w;
        }
        int s1 = g_startb[n], e1 = s1 + g_degb[n];
        float rdb = 1.f / (g_denb[n] + 1e-9f);
        for (int i = s1; i < e1; i++) {
            int e = g_permb[i];
            float a = g_logb[e] * rdb;
            float4 v = *(const float4*)(&g_hW[4][(size_t)dst[e] * FF + col]);
            acc.x += a * v.x; acc.y += a * v.y; acc.z += a * v.z; acc.w += a * v.w;
        }
        float4 sf = *(const float4*)(&g_hW[2][(size_t)n * FF + col]);
        acc.x += sf.x; acc.y += sf.y; acc.z += sf.z; acc.w += sf.w;
        *(float4*)(&g_htmp[(size_t)n * FF + col]) = acc;
        atomicAdd(&red[col], acc.x);     atomicAdd(&red[col + 1], acc.y);
        atomicAdd(&red[col + 2], acc.z); atomicAdd(&red[col + 3], acc.w);
        atomicAdd(&red[256 + col], acc.x * acc.x);     atomicAdd(&red[256 + col + 1], acc.y * acc.y);
        atomicAdd(&red[256 + col + 2], acc.z * acc.z); atomicAdd(&red[256 + col + 3], acc.w * acc.w);
    }
    __syncthreads();
    atomicAdd(&g_bnsumh[tid], (double)red[tid]);
    atomicAdd(&g_bnsumh[256 + tid], (double)red[tid + 256]);
}

// ---------------- host ----------------
extern "C" void kernel_launch(void* const* d_in, const int* in_sizes, int n_in,
                              void* d_out, int out_size) {
    const float* h0    = (const float*)d_in[0];
    const float* e0    = (const float*)d_in[1];
    const int*   src   = (const int*)d_in[2];
    const int*   dst   = (const int*)d_in[3];
    const float* We    = (const float*)d_in[4];
    const float* Ws    = (const float*)d_in[5];
    const float* Wd    = (const float*)d_in[6];
    const float* Wself = (const float*)d_in[7];
    const float* Wf    = (const float*)d_in[8];
    const float* Wb    = (const float*)d_in[9];
    const float* att_f = (const float*)d_in[10];
    const float* att_b = (const float*)d_in[11];
    const float* ge    = (const float*)d_in[12];
    const float* be    = (const float*)d_in[13];
    const float* gh    = (const float*)d_in[14];
    const float* bh    = (const float*)d_in[15];

    float* out_h = (float*)d_out;
    float* out_e = out_h + NF;

    float *hA, *hB, *eA, *eB;
    __nv_bfloat16 *ehi, *elo, *hhi, *hlo, *Wthi, *Wtlo;
    cudaGetSymbolAddress((void**)&hA, g_hA);
    cudaGetSymbolAddress((void**)&hB, g_hB);
    cudaGetSymbolAddress((void**)&eA, g_eA);
    cudaGetSymbolAddress((void**)&eB, g_eB);
    cudaGetSymbolAddress((void**)&ehi, g_ehi);
    cudaGetSymbolAddress((void**)&elo, g_elo);
    cudaGetSymbolAddress((void**)&hhi, g_hhi);
    cudaGetSymbolAddress((void**)&hlo, g_hlo);
    cudaGetSymbolAddress((void**)&Wthi, g_Wthi);
    cudaGetSymbolAddress((void**)&Wtlo, g_Wtlo);

    cudaFuncSetAttribute(gemm_mma<0>, cudaFuncAttributeMaxDynamicSharedMemorySize, SMEM_DYN);
    cudaFuncSetAttribute(gemm_mma<1>, cudaFuncAttributeMaxDynamicSharedMemorySize, SMEM_DYN);

    // once-per-call prep
    wconv<<<dim3(64, 24), 256>>>(We, Ws, Wd, Wself, Wf, Wb);
    conv_split<<<200000, 256>>>(e0, ehi, elo, EF);
    conv_split<<<12500, 256>>>(h0, hhi, hlo, NF);
    init_zero<<<196, 256>>>();
    count_deg<<<3125, 256>>>(src, dst);
    scan_starts<<<1, 1024>>>();
    fill_perm<<<3125, 256>>>(src, dst);

    const float* hin = h0;
    const float* ein = e0;
    for (int l = 0; l < 4; l++) {
        float* hout = (l == 3) ? out_h : ((l & 1) ? hB : hA);
        float* eout = (l == 3) ? out_e : ((l & 1) ? eB : eA);

        zero_layer<<<3125, 256>>>();

        gemm_mma<0><<<dim3(391, 10), 256, SMEM_DYN>>>(
            hhi, hlo, Wthi + (size_t)(l * 6) * FF * FF, Wtlo + (size_t)(l * 6) * FF * FF,
            nullptr, nullptr, nullptr, nullptr);

        gemm_mma<1><<<dim3(6250, 2), 256, SMEM_DYN>>>(
            ehi, elo, Wthi + (size_t)(l * 6 + 5) * FF * FF, Wtlo + (size_t)(l * 6 + 5) * FF * FF,
            src, dst, att_f + l * FF, att_b + l * FF);

        bn_final<<<1, 256>>>(ge + l * FF, be + l * FF, 0, 1.0f / EE);
        residual_split<0><<<200000, 256>>>(ein, eout, ehi, elo, EF);

        att_max<<<3125, 256>>>(src, dst);
        att_exp<<<3125, 256>>>(src, dst);
        agg_htmp<<<12500, 256>>>(src, dst);

        bn_final<<<1, 256>>>(gh + l * FF, bh + l * FF, 1, 1.0f / NN);
        residual_split<1><<<12500, 256>>>(hin, hout, hhi, hlo, NF);

        hin = hout;
        ein = eout;
    }
}

// round 15
// speedup vs baseline: 1.8819x; 1.1046x over previous
#include <cuda_runtime.h>
#include <cuda_bf16.h>
#include <math.h>
#include <stdint.h>

#define NN 50000
#define NPAD 50048
#define EE 800000
#define FF 256
static constexpr size_t NF  = (size_t)NN * FF;
static constexpr size_t NFP = (size_t)NPAD * FF;
static constexpr size_t EF  = (size_t)EE * FF;

// ---------------- static device scratch ----------------
__device__ float g_etmp[EF];
__device__ float g_hW[5][NF];          // 0=Ws,1=Wd,2=Wself,3=Wf,4=Wb
__device__ float g_htmp[NF];
__device__ float g_logf[EE];
__device__ float g_logb[EE];
__device__ unsigned g_maxf[NN];
__device__ unsigned g_maxb[NN];
__device__ float g_denf[NN];
__device__ float g_denb[NN];
__device__ double g_bnsum[2 * FF];
__device__ double g_bnsumh[2 * FF];
__device__ float g_scaleE[FF], g_shiftE[FF];
__device__ float g_scaleH[FF], g_shiftH[FF];
// bf16 hi/lo state (ping-pong A/B) — this IS the inter-layer h/e state
__device__ __nv_bfloat16 g_ehiA[EF], g_eloA[EF];
__device__ __nv_bfloat16 g_ehiB[EF], g_eloB[EF];
__device__ __nv_bfloat16 g_hhiA[NFP], g_hloA[NFP];
__device__ __nv_bfloat16 g_hhiB[NFP], g_hloB[NFP];
__device__ __nv_bfloat16 g_Wthi[24 * FF * FF];  // [l*6+m][n][k]; m 0..4 node mats, 5=We
__device__ __nv_bfloat16 g_Wtlo[24 * FF * FF];
// CSR
__device__ int g_degf[NN], g_degb[NN];
__device__ int g_startf[NN], g_startb[NN];
__device__ int g_curf[NN], g_curb[NN];
__device__ int g_permf[EE], g_permb[EE];

// ---------------- helpers ----------------
__device__ __forceinline__ unsigned f2u(float f) {
    unsigned u = __float_as_uint(f);
    return (u & 0x80000000u) ? ~u : (u | 0x80000000u);
}
__device__ __forceinline__ float u2f(unsigned u) {
    return (u & 0x80000000u) ? __uint_as_float(u & 0x7FFFFFFFu) : __uint_as_float(~u);
}
__device__ __forceinline__ uint32_t smem_u32(const void* p) {
    uint32_t a;
    asm("{ .reg .u64 t; cvta.to.shared.u64 t, %1; cvt.u32.u64 %0, t; }" : "=r"(a) : "l"(p));
    return a;
}
__device__ __forceinline__ void split_bf16(float x, __nv_bfloat16& h, __nv_bfloat16& l) {
    h = __float2bfloat16_rn(x);
    l = __float2bfloat16_rn(x - __bfloat162float(h));
}
__device__ __forceinline__ void cp16(uint32_t s, const void* g) {
    asm volatile("cp.async.cg.shared.global [%0], [%1], 16;" :: "r"(s), "l"(g) : "memory");
}
__device__ __forceinline__ void ldsm_x4(uint32_t& r0, uint32_t& r1, uint32_t& r2, uint32_t& r3,
                                        uint32_t addr) {
    asm volatile("ldmatrix.sync.aligned.m8n8.x4.shared.b16 {%0,%1,%2,%3}, [%4];"
                 : "=r"(r0), "=r"(r1), "=r"(r2), "=r"(r3) : "r"(addr));
}
__device__ __forceinline__ void mma16816(float* c, uint32_t a0, uint32_t a1, uint32_t a2,
                                         uint32_t a3, uint32_t b0, uint32_t b1) {
    asm volatile(
        "mma.sync.aligned.m16n8k16.row.col.f32.bf16.bf16.f32 "
        "{%0,%1,%2,%3}, {%4,%5,%6,%7}, {%8,%9}, {%0,%1,%2,%3};"
        : "+f"(c[0]), "+f"(c[1]), "+f"(c[2]), "+f"(c[3])
        : "r"(a0), "r"(a1), "r"(a2), "r"(a3), "r"(b0), "r"(b1));
}

// ---------------- mma.sync GEMM: C[128,256] = A[128,256] @ Wt^T (full N per CTA) ----------------
// 3-pass bf16 split. Rows padded to 40 bf16 (80B). Per stage:
//   Ahi[128][40] Alo[128][40] (10240B each), Bhi[256][40] Blo[256][40] (20480B each) = 61440B.
// 3 stages = 184320B. Epilogue reuses smem as C stage 128x264 fp32 (135168B).
#define STG_B 61440
#define A_ARR 10240
#define SMEM_DYN (3 * STG_B)
#define CPAD 264

__device__ __forceinline__ void load_chunk(
    uint32_t sb, int stage, int c, int tid, int rowBase, size_t matOff,
    const __nv_bfloat16* __restrict__ Ahi, const __nv_bfloat16* __restrict__ Alo,
    const __nv_bfloat16* __restrict__ Bhi, const __nv_bfloat16* __restrict__ Blo) {
    uint32_t st = sb + (uint32_t)stage * STG_B;
#pragma unroll
    for (int i = 0; i < 12; i++) {
        int j = tid + i * 256;            // 0..3071
        uint32_t sm; const __nv_bfloat16* g;
        if (j < 1024) {                    // A hi/lo: 512 vecs each
            int rem = j & 511, row = rem >> 2, part = rem & 3;
            sm = st + (j < 512 ? 0u : (uint32_t)A_ARR) + (uint32_t)row * 80 + (uint32_t)part * 16;
            const __nv_bfloat16* base = (j < 512) ? Ahi : Alo;
            g = base + (size_t)(rowBase + row) * FF + c * 32 + part * 8;
        } else {                           // B hi/lo: 1024 vecs each
            int jj = j - 1024;
            int rem = jj & 1023, row = rem >> 2, part = rem & 3;
            sm = st + 20480u + (jj < 1024 ? 0u : 20480u) + (uint32_t)row * 80 + (uint32_t)part * 16;
            const __nv_bfloat16* base = (jj < 1024) ? Bhi : Blo;
            g = base + matOff + (size_t)row * FF + c * 32 + part * 8;
        }
        cp16(sm, g);
    }
    asm volatile("cp.async.commit_group;" ::: "memory");
}

template <int EDGE>
__global__ void __launch_bounds__(256, 1)
gemm_mma(const __nv_bfloat16* __restrict__ Ahi, const __nv_bfloat16* __restrict__ Alo,
         const __nv_bfloat16* __restrict__ Bhi, const __nv_bfloat16* __restrict__ Blo,
         const int* __restrict__ src, const int* __restrict__ dst,
         const float* __restrict__ attf, const float* __restrict__ attb) {
    extern __shared__ __align__(16) char smem[];
    const uint32_t sb = smem_u32(smem);
    const int tid = threadIdx.x;
    const int lane = tid & 31, wid = tid >> 5;
    const int rowBase = blockIdx.x * 128;
    const size_t matOff = (size_t)blockIdx.y * FF * FF;
    const int wrow = (wid & 3) * 32;       // 4 warps down M
    const int wcol = (wid >> 2) * 128;     // 2 warps across N (128 cols each)

    float acc[2][16][4];
#pragma unroll
    for (int mt = 0; mt < 2; mt++)
#pragma unroll
        for (int nt = 0; nt < 16; nt++)
#pragma unroll
            for (int k = 0; k < 4; k++) acc[mt][nt][k] = 0.f;

    load_chunk(sb, 0, 0, tid, rowBase, matOff, Ahi, Alo, Bhi, Blo);
    load_chunk(sb, 1, 1, tid, rowBase, matOff, Ahi, Alo, Bhi, Blo);
    load_chunk(sb, 2, 2, tid, rowBase, matOff, Ahi, Alo, Bhi, Blo);

    for (int c = 0; c < 8; c++) {
        if (c < 6)       asm volatile("cp.async.wait_group 2;" ::: "memory");
        else if (c == 6) asm volatile("cp.async.wait_group 1;" ::: "memory");
        else             asm volatile("cp.async.wait_group 0;" ::: "memory");
        __syncthreads();
        uint32_t stg = sb + (uint32_t)(c % 3) * STG_B;
#pragma unroll
        for (int p = 0; p < 3; p++) {      // passes: Ah*Bh, Ah*Bl, Al*Bh
            uint32_t aOff = stg + ((p == 2) ? (uint32_t)A_ARR : 0u);
            uint32_t bOff = stg + 20480u + ((p == 1) ? 20480u : 0u);
#pragma unroll
            for (int k16 = 0; k16 < 2; k16++) {
                uint32_t aAddr = aOff + (uint32_t)(wrow + (lane & 15)) * 80 +
                                 (uint32_t)(k16 * 16 + (lane >> 4) * 8) * 2;
                uint32_t a0, a1, a2, a3, a4, a5, a6, a7;
                ldsm_x4(a0, a1, a2, a3, aAddr);
                ldsm_x4(a4, a5, a6, a7, aAddr + 16 * 80);
#pragma unroll
                for (int g = 0; g < 8; g++) {
                    uint32_t b0, b1, b2, b3;
                    uint32_t bAddr = bOff +
                        (uint32_t)(wcol + g * 16 + ((lane >> 4) << 3) + (lane & 7)) * 80 +
                        (uint32_t)(k16 * 16 + ((lane >> 3) & 1) * 8) * 2;
                    ldsm_x4(b0, b1, b2, b3, bAddr);
                    mma16816(acc[0][2 * g],     a0, a1, a2, a3, b0, b1);
                    mma16816(acc[0][2 * g + 1], a0, a1, a2, a3, b2, b3);
                    mma16816(acc[1][2 * g],     a4, a5, a6, a7, b0, b1);
                    mma16816(acc[1][2 * g + 1], a4, a5, a6, a7, b2, b3);
                }
            }
        }
        __syncthreads();
        if (c + 3 < 8)
            load_chunk(sb, (c + 3) % 3, c + 3, tid, rowBase, matOff, Ahi, Alo, Bhi, Blo);
    }

    // ---------------- epilogue ----------------
    const int quad = lane >> 2, q2 = (lane & 3) * 2;
    if (EDGE) {
        float* Csm = (float*)smem;   // 128 x CPAD
        __syncthreads();
#pragma unroll
        for (int mt = 0; mt < 2; mt++)
#pragma unroll
            for (int nt = 0; nt < 16; nt++) {
                int r = wrow + 16 * mt + quad;
                int cc = wcol + 8 * nt + q2;
                *(float2*)&Csm[r * CPAD + cc] = make_float2(acc[mt][nt][0], acc[mt][nt][1]);
                *(float2*)&Csm[(r + 8) * CPAD + cc] = make_float2(acc[mt][nt][2], acc[mt][nt][3]);
            }
        __syncthreads();
        {
            int r = tid >> 1, half = tid & 1;
            int gr = rowBase + r;
            int cl0 = half * 128;
            int s = src[gr], d = dst[gr];
            const float4* hs = (const float4*)(g_hW[0] + (size_t)s * FF + cl0);
            const float4* hd = (const float4*)(g_hW[1] + (size_t)d * FF + cl0);
            float4* op = (float4*)(g_etmp + (size_t)gr * FF + cl0);
            float4* cp_ = (float4*)(Csm + r * CPAD + cl0);
            const float4* af4 = (const float4*)(attf + cl0);
            const float4* ab4 = (const float4*)(attb + cl0);
            float df = 0.f, db = 0.f;
#pragma unroll
            for (int q = 0; q < 32; q++) {
                float4 v = cp_[q], a = hs[q], bb = hd[q];
                v.x += a.x + bb.x; v.y += a.y + bb.y; v.z += a.z + bb.z; v.w += a.w + bb.w;
                float4 af = af4[q], ab = ab4[q];
                df += v.x * af.x + v.y * af.y + v.z * af.z + v.w * af.w;
                db += v.x * ab.x + v.y * ab.y + v.z * ab.z + v.w * ab.w;
                op[q] = v;
                cp_[q] = v;
            }
            df += __shfl_xor_sync(0xffffffffu, df, 1);
            db += __shfl_xor_sync(0xffffffffu, db, 1);
            if (half == 0) { g_logf[gr] = df; g_logb[gr] = db; }
        }
        __syncthreads();
        {
            float s = 0.f, s2 = 0.f;
#pragma unroll 8
            for (int r = 0; r < 128; r++) {
                float v = Csm[r * CPAD + tid];
                s += v; s2 += v * v;
            }
            atomicAdd(&g_bnsum[tid], (double)s);
            atomicAdd(&g_bnsum[FF + tid], (double)s2);
        }
    } else {
        float* W = g_hW[blockIdx.y];
#pragma unroll
        for (int mt = 0; mt < 2; mt++) {
            int gr = rowBase + wrow + 16 * mt + quad;
#pragma unroll
            for (int nt = 0; nt < 16; nt++) {
                int gcol = wcol + 8 * nt + q2;
                if (gr < NN)
                    *(float2*)&W[(size_t)gr * FF + gcol] = make_float2(acc[mt][nt][0], acc[mt][nt][1]);
                if (gr + 8 < NN)
                    *(float2*)&W[(size_t)(gr + 8) * FF + gcol] = make_float2(acc[mt][nt][2], acc[mt][nt][3]);
            }
        }
    }
}

// ---------------- weight transpose + split (once) ----------------
__global__ void wconv(const float* __restrict__ We, const float* __restrict__ Ws,
                      const float* __restrict__ Wd, const float* __restrict__ Wself,
                      const float* __restrict__ Wf, const float* __restrict__ Wb) {
    int mi = blockIdx.y, l = mi / 6, m = mi % 6;
    const float* W = (m == 0) ? Ws : (m == 1) ? Wd : (m == 2) ? Wself :
                     (m == 3) ? Wf : (m == 4) ? Wb : We;
    W += (size_t)l * FF * FF;
    __nv_bfloat16* hi = g_Wthi + (size_t)mi * FF * FF;
    __nv_bfloat16* lo = g_Wtlo + (size_t)mi * FF * FF;
    int idx = (blockIdx.x * 256 + threadIdx.x) * 4;
#pragma unroll
    for (int t = 0; t < 4; t++) {
        int o = idx + t, n = o >> 8, k = o & 255;
        __nv_bfloat16 h, lw;
        split_bf16(W[(size_t)k * FF + n], h, lw);   // Wt[n][k] = W[k][n]
        hi[o] = h; lo[o] = lw;
    }
}

// ---------------- fp32 -> bf16 hi/lo split (initial inputs) ----------------
__global__ void conv_split(const float* __restrict__ x, __nv_bfloat16* __restrict__ hi,
                           __nv_bfloat16* __restrict__ lo, size_t total) {
    size_t i = ((size_t)blockIdx.x * blockDim.x + threadIdx.x) * 4;
    if (i >= total) return;
    float4 v = *(const float4*)(x + i);
    __nv_bfloat16 h0, l0, h1, l1, h2, l2, h3, l3;
    split_bf16(v.x, h0, l0); split_bf16(v.y, h1, l1);
    split_bf16(v.z, h2, l2); split_bf16(v.w, h3, l3);
    __nv_bfloat162 a, b, c, d;
    a.x = h0; a.y = h1; b.x = h2; b.y = h3;
    c.x = l0; c.y = l1; d.x = l2; d.y = l3;
    *(__nv_bfloat162*)(hi + i) = a; *(__nv_bfloat162*)(hi + i + 2) = b;
    *(__nv_bfloat162*)(lo + i) = c; *(__nv_bfloat162*)(lo + i + 2) = d;
}

// ---------------- once-per-call init ----------------
__global__ void init_zero() {
    int i = blockIdx.x * 256 + threadIdx.x;
    if (i < NN) { g_degf[i] = 0; g_degb[i] = 0; }
    if (i < 48 * FF) {
        size_t base = (size_t)NN * FF + i;
        __nv_bfloat16 z = __float2bfloat16(0.f);
        g_hhiA[base] = z; g_hloA[base] = z;
        g_hhiB[base] = z; g_hloB[base] = z;
    }
}
__global__ void count_deg(const int* __restrict__ src, const int* __restrict__ dst) {
    int e = blockIdx.x * 256 + threadIdx.x;
    if (e >= EE) return;
    atomicAdd(&g_degf[dst[e]], 1);
    atomicAdd(&g_degb[src[e]], 1);
}
__global__ void scan_starts() {   // single block, 1024 threads
    __shared__ int sh[1024];
    __shared__ int carry;
    int tid = threadIdx.x;
    for (int a = 0; a < 2; a++) {
        const int* deg = a ? g_degb : g_degf;
        int* start = a ? g_startb : g_startf;
        int* cur = a ? g_curb : g_curf;
        if (tid == 0) carry = 0;
        __syncthreads();
        for (int base = 0; base < NN; base += 1024) {
            int n = base + tid;
            int v = (n < NN) ? deg[n] : 0;
            sh[tid] = v;
            __syncthreads();
            for (int off = 1; off < 1024; off <<= 1) {
                int t = (tid >= off) ? sh[tid - off] : 0;
                __syncthreads();
                sh[tid] += t;
                __syncthreads();
            }
            int excl = sh[tid] - v + carry;
            if (n < NN) { start[n] = excl; cur[n] = excl; }
            __syncthreads();
            if (tid == 0) carry += sh[1023];
            __syncthreads();
        }
    }
}
__global__ void fill_perm(const int* __restrict__ src, const int* __restrict__ dst) {
    int e = blockIdx.x * 256 + threadIdx.x;
    if (e >= EE) return;
    g_permf[atomicAdd(&g_curf[dst[e]], 1)] = e;
    g_permb[atomicAdd(&g_curb[src[e]], 1)] = e;
}

// ---------------- per-layer zero (logits now single-writer: no zero needed) ----------------
__global__ void zero_layer() {
    int i = blockIdx.x * 256 + threadIdx.x;
    if (i < NN) { g_maxf[i] = 0u; g_maxb[i] = 0u; g_denf[i] = 0.f; g_denb[i] = 0.f; }
    if (i < 2 * FF) { g_bnsum[i] = 0.0; g_bnsumh[i] = 0.0; }
}

// ---------------- BN finalize ----------------
__global__ void bn_final(const float* __restrict__ g, const float* __restrict__ b,
                         int isH, float invM) {
    int f = threadIdx.x;
    const double* sums = isH ? g_bnsumh : g_bnsum;
    float mu = (float)(sums[f] * (double)invM);
    float var = (float)(sums[FF + f] * (double)invM) - mu * mu;
    float sc = rsqrtf(var + 1e-5f) * g[f];
    float sh = b[f] - mu * sc;
    if (isH) { g_scaleH[f] = sc; g_shiftH[f] = sh; }
    else     { g_scaleE[f] = sc; g_shiftE[f] = sh; }
}

// ---------------- out = (hi+lo) + relu(tmp*scale+shift) ----------------
// WF32: write fp32 result; WSPLIT: write bf16 hi/lo (next layer state)
template <int ISH, int WF32, int WSPLIT>
__global__ void residual2(const __nv_bfloat16* __restrict__ in_hi,
                          const __nv_bfloat16* __restrict__ in_lo,
                          float* __restrict__ outf,
                          __nv_bfloat16* __restrict__ out_hi,
                          __nv_bfloat16* __restrict__ out_lo, size_t total) {
    size_t i = ((size_t)blockIdx.x * blockDim.x + threadIdx.x) * 4;
    if (i >= total) return;
    const float* tmp = ISH ? g_htmp : g_etmp;
    const float* scale = ISH ? g_scaleH : g_scaleE;
    const float* shift = ISH ? g_shiftH : g_shiftE;
    int c = (int)(i & (FF - 1));
    __nv_bfloat162 xh0 = *(const __nv_bfloat162*)(in_hi + i);
    __nv_bfloat162 xh1 = *(const __nv_bfloat162*)(in_hi + i + 2);
    __nv_bfloat162 xl0 = *(const __nv_bfloat162*)(in_lo + i);
    __nv_bfloat162 xl1 = *(const __nv_bfloat162*)(in_lo + i + 2);
    float4 x;
    x.x = __bfloat162float(xh0.x) + __bfloat162float(xl0.x);
    x.y = __bfloat162float(xh0.y) + __bfloat162float(xl0.y);
    x.z = __bfloat162float(xh1.x) + __bfloat162float(xl1.x);
    x.w = __bfloat162float(xh1.y) + __bfloat162float(xl1.y);
    float4 t = *(const float4*)(tmp + i);
    float4 o;
    o.x = x.x + fmaxf(fmaf(t.x, scale[c],     shift[c]),     0.f);
    o.y = x.y + fmaxf(fmaf(t.y, scale[c + 1], shift[c + 1]), 0.f);
    o.z = x.z + fmaxf(fmaf(t.z, scale[c + 2], shift[c + 2]), 0.f);
    o.w = x.w + fmaxf(fmaf(t.w, scale[c + 3], shift[c + 3]), 0.f);
    if (WF32) *(float4*)(outf + i) = o;
    if (WSPLIT) {
        __nv_bfloat16 h0, l0, h1, l1, h2, l2, h3, l3;
        split_bf16(o.x, h0, l0); split_bf16(o.y, h1, l1);
        split_bf16(o.z, h2, l2); split_bf16(o.w, h3, l3);
        __nv_bfloat162 a, b, cc, d;
        a.x = h0; a.y = h1; b.x = h2; b.y = h3;
        cc.x = l0; cc.y = l1; d.x = l2; d.y = l3;
        *(__nv_bfloat162*)(out_hi + i) = a; *(__nv_bfloat162*)(out_hi + i + 2) = b;
        *(__nv_bfloat162*)(out_lo + i) = cc; *(__nv_bfloat162*)(out_lo + i + 2) = d;
    }
}

// ---------------- attention ----------------
__global__ void att_max(const int* __restrict__ src, const int* __restrict__ dst) {
    int e = blockIdx.x * 256 + threadIdx.x;
    if (e >= EE) return;
    float lf = g_logf[e]; lf = lf > 0.f ? lf : 0.2f * lf; g_logf[e] = lf;
    float lb = g_logb[e]; lb = lb > 0.f ? lb : 0.2f * lb; g_logb[e] = lb;
    atomicMax(&g_maxf[dst[e]], f2u(lf));
    atomicMax(&g_maxb[src[e]], f2u(lb));
}
__global__ void att_exp(const int* __restrict__ src, const int* __restrict__ dst) {
    int e = blockIdx.x * 256 + threadIdx.x;
    if (e >= EE) return;
    int d = dst[e], s = src[e];
    float exf = expf(g_logf[e] - u2f(g_maxf[d]));
    g_logf[e] = exf;
    atomicAdd(&g_denf[d], exf);
    float exb = expf(g_logb[e] - u2f(g_maxb[s]));
    g_logb[e] = exb;
    atomicAdd(&g_denb[s], exb);
}

// ---------------- CSR aggregation + htmp + h BN stats ----------------
__global__ void __launch_bounds__(256)
agg_htmp(const int* __restrict__ src, const int* __restrict__ dst) {
    __shared__ float red[512];
    int tid = threadIdx.x;
    red[tid] = 0.f; red[tid + 256] = 0.f;
    __syncthreads();
    int g = tid >> 6, lane = tid & 63;
    int n = blockIdx.x * 4 + g;
    if (n < NN) {
        int col = lane * 4;
        float4 acc = make_float4(0.f, 0.f, 0.f, 0.f);
        int s0 = g_startf[n], e0 = s0 + g_degf[n];
        float rdf = 1.f / (g_denf[n] + 1e-9f);
        for (int i = s0; i < e0; i++) {
            int e = g_permf[i];
            float a = g_logf[e] * rdf;
            float4 v = *(const float4*)(&g_hW[3][(size_t)src[e] * FF + col]);
            acc.x += a * v.x; acc.y += a * v.y; acc.z += a * v.z; acc.w += a * v.w;
        }
        int s1 = g_startb[n], e1 = s1 + g_degb[n];
        float rdb = 1.f / (g_denb[n] + 1e-9f);
        for (int i = s1; i < e1; i++) {
            int e = g_permb[i];
            float a = g_logb[e] * rdb;
            float4 v = *(const float4*)(&g_hW[4][(size_t)dst[e] * FF + col]);
            acc.x += a * v.x; acc.y += a * v.y; acc.z += a * v.z; acc.w += a * v.w;
        }
        float4 sf = *(const float4*)(&g_hW[2][(size_t)n * FF + col]);
        acc.x += sf.x; acc.y += sf.y; acc.z += sf.z; acc.w += sf.w;
        *(float4*)(&g_htmp[(size_t)n * FF + col]) = acc;
        atomicAdd(&red[col], acc.x);     atomicAdd(&red[col + 1], acc.y);
        atomicAdd(&red[col + 2], acc.z); atomicAdd(&red[col + 3], acc.w);
        atomicAdd(&red[256 + col], acc.x * acc.x);     atomicAdd(&red[256 + col + 1], acc.y * acc.y);
        atomicAdd(&red[256 + col + 2], acc.z * acc.z); atomicAdd(&red[256 + col + 3], acc.w * acc.w);
    }
    __syncthreads();
    atomicAdd(&g_bnsumh[tid], (double)red[tid]);
    atomicAdd(&g_bnsumh[256 + tid], (double)red[tid + 256]);
}

// ---------------- host ----------------
extern "C" void kernel_launch(void* const* d_in, const int* in_sizes, int n_in,
                              void* d_out, int out_size) {
    const float* h0    = (const float*)d_in[0];
    const float* e0    = (const float*)d_in[1];
    const int*   src   = (const int*)d_in[2];
    const int*   dst   = (const int*)d_in[3];
    const float* We    = (const float*)d_in[4];
    const float* Ws    = (const float*)d_in[5];
    const float* Wd    = (const float*)d_in[6];
    const float* Wself = (const float*)d_in[7];
    const float* Wf    = (const float*)d_in[8];
    const float* Wb    = (const float*)d_in[9];
    const float* att_f = (const float*)d_in[10];
    const float* att_b = (const float*)d_in[11];
    const float* ge    = (const float*)d_in[12];
    const float* be    = (const float*)d_in[13];
    const float* gh    = (const float*)d_in[14];
    const float* bh    = (const float*)d_in[15];

    float* out_h = (float*)d_out;
    float* out_e = out_h + NF;

    __nv_bfloat16 *ehiA, *eloA, *ehiB, *eloB, *hhiA, *hloA, *hhiB, *hloB, *Wthi, *Wtlo;
    cudaGetSymbolAddress((void**)&ehiA, g_ehiA);
    cudaGetSymbolAddress((void**)&eloA, g_eloA);
    cudaGetSymbolAddress((void**)&ehiB, g_ehiB);
    cudaGetSymbolAddress((void**)&eloB, g_eloB);
    cudaGetSymbolAddress((void**)&hhiA, g_hhiA);
    cudaGetSymbolAddress((void**)&hloA, g_hloA);
    cudaGetSymbolAddress((void**)&hhiB, g_hhiB);
    cudaGetSymbolAddress((void**)&hloB, g_hloB);
    cudaGetSymbolAddress((void**)&Wthi, g_Wthi);
    cudaGetSymbolAddress((void**)&Wtlo, g_Wtlo);

    cudaFuncSetAttribute(gemm_mma<0>, cudaFuncAttributeMaxDynamicSharedMemorySize, SMEM_DYN);
    cudaFuncSetAttribute(gemm_mma<1>, cudaFuncAttributeMaxDynamicSharedMemorySize, SMEM_DYN);

    // once-per-call prep
    wconv<<<dim3(64, 24), 256>>>(We, Ws, Wd, Wself, Wf, Wb);
    conv_split<<<200000, 256>>>(e0, ehiA, eloA, EF);
    conv_split<<<12500, 256>>>(h0, hhiA, hloA, NF);
    init_zero<<<196, 256>>>();
    count_deg<<<3125, 256>>>(src, dst);
    scan_starts<<<1, 1024>>>();
    fill_perm<<<3125, 256>>>(src, dst);

    for (int l = 0; l < 4; l++) {
        __nv_bfloat16 *ehi_in  = (l & 1) ? ehiB : ehiA, *elo_in  = (l & 1) ? eloB : eloA;
        __nv_bfloat16 *ehi_out = (l & 1) ? ehiA : ehiB, *elo_out = (l & 1) ? eloA : eloB;
        __nv_bfloat16 *hhi_in  = (l & 1) ? hhiB : hhiA, *hlo_in  = (l & 1) ? hloB : hloA;
        __nv_bfloat16 *hhi_out = (l & 1) ? hhiA : hhiB, *hlo_out = (l & 1) ? hloA : hloB;

        zero_layer<<<196, 256>>>();

        gemm_mma<0><<<dim3(391, 5), 256, SMEM_DYN>>>(
            hhi_in, hlo_in, Wthi + (size_t)(l * 6) * FF * FF, Wtlo + (size_t)(l * 6) * FF * FF,
            nullptr, nullptr, nullptr, nullptr);

        gemm_mma<1><<<dim3(6250, 1), 256, SMEM_DYN>>>(
            ehi_in, elo_in, Wthi + (size_t)(l * 6 + 5) * FF * FF, Wtlo + (size_t)(l * 6 + 5) * FF * FF,
            src, dst, att_f + l * FF, att_b + l * FF);

        bn_final<<<1, 256>>>(ge + l * FF, be + l * FF, 0, 1.0f / EE);
        if (l < 3)
            residual2<0, 0, 1><<<200000, 256>>>(ehi_in, elo_in, nullptr, ehi_out, elo_out, EF);
        else
            residual2<0, 1, 0><<<200000, 256>>>(ehi_in, elo_in, out_e, nullptr, nullptr, EF);

        att_max<<<3125, 256>>>(src, dst);
        att_exp<<<3125, 256>>>(src, dst);
        agg_htmp<<<12500, 256>>>(src, dst);

        bn_final<<<1, 256>>>(gh + l * FF, bh + l * FF, 1, 1.0f / NN);
        if (l < 3)
            residual2<1, 0, 1><<<12500, 256>>>(hhi_in, hlo_in, nullptr, hhi_out, hlo_out, NF);
        else
            residual2<1, 1, 0><<<12500, 256>>>(hhi_in, hlo_in, out_h, nullptr, nullptr, NF);
    }
}